// round 1
// baseline (speedup 1.0000x reference)
#include <cuda_runtime.h>

// ---------------- problem constants ----------------
#define B_    8
#define H_    192
#define W_    192
#define C_    128
#define DW_   256
#define NPIX  (B_*H_*W_)        // 294912
#define PIXPB (H_*W_)           // 36864 pixels per batch
#define EPS   1e-6f

// ---------------- launch geometry ----------------
#define WARPS      8
#define THREADS    256
#define PPW        4                         // pixels per warp per inner iter
#define ITERS      16
#define PIXPERBLK  (WARPS*PPW*ITERS)         // 512
#define NBLK       (NPIX/PIXPERBLK)          // 576
#define BLKPB      (PIXPB/PIXPERBLK)         // 72 blocks per batch (exact)

// ---------------- scratch (static device memory; no allocation) ----------------
__device__ float g_s[NPIX*C_];       // gated spatial branch (pre-SE)
__device__ float g_xm[NPIX*C_];      // x + beta*spatial  (input to FFN branch)
__device__ float g_gpart[NBLK*C_];   // per-block GAP partial sums (deterministic)
__device__ float g_att[B_*C_];       // SE attention per batch

// =====================================================================
// Kernel 1: LN1 -> w1 (128->256) + b1 -> dw affine -> SimpleGate -> g_s
//           + per-block per-channel partial sums for GAP
// =====================================================================
__global__ void __launch_bounds__(THREADS)
k1_spatial_gate(const float* __restrict__ x,
                const float* __restrict__ ln1s, const float* __restrict__ ln1b,
                const float* __restrict__ w1,   const float* __restrict__ b1,
                const float* __restrict__ wdw,  const float* __restrict__ bdw)
{
    extern __shared__ float sm[];
    float* w1s = sm;                      // 128*256 = 32768 floats
    float* ts  = sm + C_*DW_;             // 8 warps * 4 pix * 128 = 4096 floats
    __shared__ float gapb[C_];

    const int tid = threadIdx.x, wid = tid >> 5, lid = tid & 31;

    // stage w1 into smem (float4)
    for (int i = tid; i < (C_*DW_)/4; i += THREADS)
        ((float4*)w1s)[i] = ((const float4*)w1)[i];
    if (tid < C_) gapb[tid] = 0.f;

    // per-lane parameter vectors (lane owns channels 4*lid .. 4*lid+3; +128 for B half)
    const float4 l1s = ((const float4*)ln1s)[lid];
    const float4 l1b = ((const float4*)ln1b)[lid];
    const float4 b1A = ((const float4*)b1 )[lid];
    const float4 b1B = ((const float4*)b1 )[lid + 32];
    const float4 dwA = ((const float4*)wdw)[lid];
    const float4 dwB = ((const float4*)wdw)[lid + 32];
    const float4 dbA = ((const float4*)bdw)[lid];
    const float4 dbB = ((const float4*)bdw)[lid + 32];
    __syncthreads();

    float gl0 = 0.f, gl1 = 0.f, gl2 = 0.f, gl3 = 0.f;
    float* tw = ts + wid * (PPW*C_);

    for (int it = 0; it < ITERS; ++it) {
        const int p0 = blockIdx.x*PIXPERBLK + it*(WARPS*PPW) + wid*PPW;

        // --- LN1 and stage t into smem ---
        #pragma unroll
        for (int q = 0; q < PPW; ++q) {
            const int p = p0 + q;
            float4 xv = ((const float4*)x)[p*32 + lid];
            float s1 = xv.x + xv.y + xv.z + xv.w;
            float s2 = xv.x*xv.x + xv.y*xv.y + xv.z*xv.z + xv.w*xv.w;
            #pragma unroll
            for (int o = 16; o; o >>= 1) {
                s1 += __shfl_xor_sync(0xffffffffu, s1, o);
                s2 += __shfl_xor_sync(0xffffffffu, s2, o);
            }
            const float mu = s1 * (1.f/C_);
            const float rs = rsqrtf(fmaxf(s2*(1.f/C_) - mu*mu, 0.f) + EPS);
            float4 t;
            t.x = (xv.x - mu)*rs*l1s.x + l1b.x;
            t.y = (xv.y - mu)*rs*l1s.y + l1b.y;
            t.z = (xv.z - mu)*rs*l1s.z + l1b.z;
            t.w = (xv.w - mu)*rs*l1s.w + l1b.w;
            ((float4*)(tw + q*C_))[lid] = t;
        }
        __syncwarp();

        // --- u = t @ w1 : lane accumulates outputs {4lid..4lid+3} and {128+4lid..} ---
        float acc[PPW][8];
        #pragma unroll
        for (int q = 0; q < PPW; ++q)
            #pragma unroll
            for (int j = 0; j < 8; ++j) acc[q][j] = 0.f;

        #pragma unroll 4
        for (int k = 0; k < C_; ++k) {
            const float4 wa = ((const float4*)(w1s + k*DW_))[lid];
            const float4 wb = ((const float4*)(w1s + k*DW_ + C_))[lid];
            #pragma unroll
            for (int q = 0; q < PPW; ++q) {
                const float tk = tw[q*C_ + k];
                acc[q][0] += tk*wa.x; acc[q][1] += tk*wa.y;
                acc[q][2] += tk*wa.z; acc[q][3] += tk*wa.w;
                acc[q][4] += tk*wb.x; acc[q][5] += tk*wb.y;
                acc[q][6] += tk*wb.z; acc[q][7] += tk*wb.w;
            }
        }

        // --- +b1, dw affine, gate, store s, GAP partial ---
        #pragma unroll
        for (int q = 0; q < PPW; ++q) {
            const int p = p0 + q;
            float4 uA, uB, sv;
            uA.x = (acc[q][0] + b1A.x)*dwA.x + dbA.x;
            uA.y = (acc[q][1] + b1A.y)*dwA.y + dbA.y;
            uA.z = (acc[q][2] + b1A.z)*dwA.z + dbA.z;
            uA.w = (acc[q][3] + b1A.w)*dwA.w + dbA.w;
            uB.x = (acc[q][4] + b1B.x)*dwB.x + dbB.x;
            uB.y = (acc[q][5] + b1B.y)*dwB.y + dbB.y;
            uB.z = (acc[q][6] + b1B.z)*dwB.z + dbB.z;
            uB.w = (acc[q][7] + b1B.w)*dwB.w + dbB.w;
            sv.x = uA.x*uB.x; sv.y = uA.y*uB.y; sv.z = uA.z*uB.z; sv.w = uA.w*uB.w;
            ((float4*)g_s)[p*32 + lid] = sv;
            gl0 += sv.x; gl1 += sv.y; gl2 += sv.z; gl3 += sv.w;
        }
        __syncwarp();
    }

    // per-block channel sums (smem atomics across 8 warps; channel-aligned lanes)
    atomicAdd(&gapb[4*lid + 0], gl0);
    atomicAdd(&gapb[4*lid + 1], gl1);
    atomicAdd(&gapb[4*lid + 2], gl2);
    atomicAdd(&gapb[4*lid + 3], gl3);
    __syncthreads();
    if (tid < C_) g_gpart[blockIdx.x*C_ + tid] = gapb[tid];
}

// =====================================================================
// Kernel 2: deterministic GAP reduce + SE dense: att = (gap/PIXPB)@wse + bse
// grid = B_ blocks, 128 threads
// =====================================================================
__global__ void k2_se(const float* __restrict__ wse, const float* __restrict__ bse)
{
    __shared__ float gap[C_];
    const int b = blockIdx.x, j = threadIdx.x;
    float s = 0.f;
    for (int blk = 0; blk < BLKPB; ++blk)
        s += g_gpart[(b*BLKPB + blk)*C_ + j];
    gap[j] = s * (1.f/PIXPB);
    __syncthreads();
    float a = bse[j];
    #pragma unroll 4
    for (int k = 0; k < C_; ++k)
        a += gap[k] * wse[k*C_ + j];
    g_att[b*C_ + j] = a;
}

// =====================================================================
// Kernel 3a: v = s*att -> w2 (128->128) + b2 -> xm = x + beta*y
// =====================================================================
__global__ void __launch_bounds__(THREADS)
k3a_project(const float* __restrict__ x, const float* __restrict__ w2,
            const float* __restrict__ b2, const float* __restrict__ beta)
{
    extern __shared__ float sm[];
    float* w2s = sm;                 // 128*128 = 16384 floats
    float* ts  = sm + C_*C_;         // 4096 floats

    const int tid = threadIdx.x, wid = tid >> 5, lid = tid & 31;
    for (int i = tid; i < (C_*C_)/4; i += THREADS)
        ((float4*)w2s)[i] = ((const float4*)w2)[i];

    const int b = blockIdx.x / BLKPB;
    const float4 attv  = ((const float4*)(g_att + b*C_))[lid];
    const float4 b2v   = ((const float4*)b2  )[lid];
    const float4 betav = ((const float4*)beta)[lid];
    __syncthreads();

    float* tw = ts + wid * (PPW*C_);

    for (int it = 0; it < ITERS; ++it) {
        const int p0 = blockIdx.x*PIXPERBLK + it*(WARPS*PPW) + wid*PPW;
        #pragma unroll
        for (int q = 0; q < PPW; ++q) {
            const int p = p0 + q;
            float4 svv = ((const float4*)g_s)[p*32 + lid];
            float4 v;
            v.x = svv.x*attv.x; v.y = svv.y*attv.y; v.z = svv.z*attv.z; v.w = svv.w*attv.w;
            ((float4*)(tw + q*C_))[lid] = v;
        }
        __syncwarp();

        float acc[PPW][4];
        #pragma unroll
        for (int q = 0; q < PPW; ++q)
            #pragma unroll
            for (int j = 0; j < 4; ++j) acc[q][j] = 0.f;

        #pragma unroll 4
        for (int k = 0; k < C_; ++k) {
            const float4 w = ((const float4*)(w2s + k*C_))[lid];
            #pragma unroll
            for (int q = 0; q < PPW; ++q) {
                const float tk = tw[q*C_ + k];
                acc[q][0] += tk*w.x; acc[q][1] += tk*w.y;
                acc[q][2] += tk*w.z; acc[q][3] += tk*w.w;
            }
        }

        #pragma unroll
        for (int q = 0; q < PPW; ++q) {
            const int p = p0 + q;
            float4 xv = ((const float4*)x)[p*32 + lid];
            float4 xm;
            xm.x = xv.x + betav.x*(acc[q][0] + b2v.x);
            xm.y = xv.y + betav.y*(acc[q][1] + b2v.y);
            xm.z = xv.z + betav.z*(acc[q][2] + b2v.z);
            xm.w = xv.w + betav.w*(acc[q][3] + b2v.w);
            ((float4*)g_xm)[p*32 + lid] = xm;
        }
        __syncwarp();
    }
}

// =====================================================================
// Kernel 3b: LN2 -> wf1 (128->256)+bf1 -> gate -> wf2 (128->128)+bf2
//            -> out = xm + gamma*c
// =====================================================================
__global__ void __launch_bounds__(THREADS)
k3b_ffn(const float* __restrict__ ln2s, const float* __restrict__ ln2b,
        const float* __restrict__ wf1,  const float* __restrict__ bf1,
        const float* __restrict__ wf2,  const float* __restrict__ bf2,
        const float* __restrict__ gamma, float* __restrict__ out)
{
    extern __shared__ float sm[];
    float* wf1s = sm;                       // 32768 floats
    float* wf2s = sm + C_*DW_;              // 16384 floats
    float* ts   = sm + C_*DW_ + C_*C_;      // 4096 floats

    const int tid = threadIdx.x, wid = tid >> 5, lid = tid & 31;
    for (int i = tid; i < (C_*DW_)/4; i += THREADS)
        ((float4*)wf1s)[i] = ((const float4*)wf1)[i];
    for (int i = tid; i < (C_*C_)/4; i += THREADS)
        ((float4*)wf2s)[i] = ((const float4*)wf2)[i];

    const float4 l2s  = ((const float4*)ln2s)[lid];
    const float4 l2b  = ((const float4*)ln2b)[lid];
    const float4 bf1A = ((const float4*)bf1)[lid];
    const float4 bf1B = ((const float4*)bf1)[lid + 32];
    const float4 bf2v = ((const float4*)bf2)[lid];
    const float4 gamv = ((const float4*)gamma)[lid];
    __syncthreads();

    float* tw = ts + wid * (PPW*C_);

    for (int it = 0; it < ITERS; ++it) {
        const int p0 = blockIdx.x*PIXPERBLK + it*(WARPS*PPW) + wid*PPW;

        float4 xm[PPW];
        #pragma unroll
        for (int q = 0; q < PPW; ++q) {
            const int p = p0 + q;
            xm[q] = ((const float4*)g_xm)[p*32 + lid];
            float s1 = xm[q].x + xm[q].y + xm[q].z + xm[q].w;
            float s2 = xm[q].x*xm[q].x + xm[q].y*xm[q].y + xm[q].z*xm[q].z + xm[q].w*xm[q].w;
            #pragma unroll
            for (int o = 16; o; o >>= 1) {
                s1 += __shfl_xor_sync(0xffffffffu, s1, o);
                s2 += __shfl_xor_sync(0xffffffffu, s2, o);
            }
            const float mu = s1 * (1.f/C_);
            const float rs = rsqrtf(fmaxf(s2*(1.f/C_) - mu*mu, 0.f) + EPS);
            float4 t;
            t.x = (xm[q].x - mu)*rs*l2s.x + l2b.x;
            t.y = (xm[q].y - mu)*rs*l2s.y + l2b.y;
            t.z = (xm[q].z - mu)*rs*l2s.z + l2b.z;
            t.w = (xm[q].w - mu)*rs*l2s.w + l2b.w;
            ((float4*)(tw + q*C_))[lid] = t;
        }
        __syncwarp();

        // u = t @ wf1
        float acc[PPW][8];
        #pragma unroll
        for (int q = 0; q < PPW; ++q)
            #pragma unroll
            for (int j = 0; j < 8; ++j) acc[q][j] = 0.f;

        #pragma unroll 4
        for (int k = 0; k < C_; ++k) {
            const float4 wa = ((const float4*)(wf1s + k*DW_))[lid];
            const float4 wb = ((const float4*)(wf1s + k*DW_ + C_))[lid];
            #pragma unroll
            for (int q = 0; q < PPW; ++q) {
                const float tk = tw[q*C_ + k];
                acc[q][0] += tk*wa.x; acc[q][1] += tk*wa.y;
                acc[q][2] += tk*wa.z; acc[q][3] += tk*wa.w;
                acc[q][4] += tk*wb.x; acc[q][5] += tk*wb.y;
                acc[q][6] += tk*wb.z; acc[q][7] += tk*wb.w;
            }
        }
        __syncwarp();

        // gate, restage c into ts
        #pragma unroll
        for (int q = 0; q < PPW; ++q) {
            float4 uA, uB, cv;
            uA.x = acc[q][0] + bf1A.x; uA.y = acc[q][1] + bf1A.y;
            uA.z = acc[q][2] + bf1A.z; uA.w = acc[q][3] + bf1A.w;
            uB.x = acc[q][4] + bf1B.x; uB.y = acc[q][5] + bf1B.y;
            uB.z = acc[q][6] + bf1B.z; uB.w = acc[q][7] + bf1B.w;
            cv.x = uA.x*uB.x; cv.y = uA.y*uB.y; cv.z = uA.z*uB.z; cv.w = uA.w*uB.w;
            ((float4*)(tw + q*C_))[lid] = cv;
        }
        __syncwarp();

        // z = c @ wf2
        float acc2[PPW][4];
        #pragma unroll
        for (int q = 0; q < PPW; ++q)
            #pragma unroll
            for (int j = 0; j < 4; ++j) acc2[q][j] = 0.f;

        #pragma unroll 4
        for (int k = 0; k < C_; ++k) {
            const float4 w = ((const float4*)(wf2s + k*C_))[lid];
            #pragma unroll
            for (int q = 0; q < PPW; ++q) {
                const float tk = tw[q*C_ + k];
                acc2[q][0] += tk*w.x; acc2[q][1] += tk*w.y;
                acc2[q][2] += tk*w.z; acc2[q][3] += tk*w.w;
            }
        }

        #pragma unroll
        for (int q = 0; q < PPW; ++q) {
            const int p = p0 + q;
            float4 o;
            o.x = xm[q].x + gamv.x*(acc2[q][0] + bf2v.x);
            o.y = xm[q].y + gamv.y*(acc2[q][1] + bf2v.y);
            o.z = xm[q].z + gamv.z*(acc2[q][2] + bf2v.z);
            o.w = xm[q].w + gamv.w*(acc2[q][3] + bf2v.w);
            ((float4*)out)[p*32 + lid] = o;
        }
        __syncwarp();
    }
}

// =====================================================================
// launch
// =====================================================================
extern "C" void kernel_launch(void* const* d_in, const int* in_sizes, int n_in,
                              void* d_out, int out_size)
{
    (void)in_sizes; (void)n_in; (void)out_size;
    const float* x     = (const float*)d_in[0];
    const float* ln1s  = (const float*)d_in[1];
    const float* ln1b  = (const float*)d_in[2];
    const float* w1    = (const float*)d_in[3];
    const float* b1    = (const float*)d_in[4];
    const float* wdw   = (const float*)d_in[5];
    const float* bdw   = (const float*)d_in[6];
    const float* wse   = (const float*)d_in[7];
    const float* bse   = (const float*)d_in[8];
    const float* w2    = (const float*)d_in[9];
    const float* b2    = (const float*)d_in[10];
    const float* ln2s  = (const float*)d_in[11];
    const float* ln2b  = (const float*)d_in[12];
    const float* wf1   = (const float*)d_in[13];
    const float* bf1   = (const float*)d_in[14];
    const float* wf2   = (const float*)d_in[15];
    const float* bf2   = (const float*)d_in[16];
    const float* beta  = (const float*)d_in[17];
    const float* gamma = (const float*)d_in[18];
    float* out = (float*)d_out;

    const size_t smem1  = (size_t)(C_*DW_ + WARPS*PPW*C_) * 4;            // 147456
    const size_t smem3a = (size_t)(C_*C_  + WARPS*PPW*C_) * 4;            // 81920
    const size_t smem3b = (size_t)(C_*DW_ + C_*C_ + WARPS*PPW*C_) * 4;    // 212992

    cudaFuncSetAttribute(k1_spatial_gate, cudaFuncAttributeMaxDynamicSharedMemorySize, (int)smem1);
    cudaFuncSetAttribute(k3a_project,     cudaFuncAttributeMaxDynamicSharedMemorySize, (int)smem3a);
    cudaFuncSetAttribute(k3b_ffn,         cudaFuncAttributeMaxDynamicSharedMemorySize, (int)smem3b);

    k1_spatial_gate<<<NBLK, THREADS, smem1>>>(x, ln1s, ln1b, w1, b1, wdw, bdw);
    k2_se<<<B_, C_>>>(wse, bse);
    k3a_project<<<NBLK, THREADS, smem3a>>>(x, w2, b2, beta);
    k3b_ffn<<<NBLK, THREADS, smem3b>>>(ln2s, ln2b, wf1, bf1, wf2, bf2, gamma, out);
}

// round 2
// speedup vs baseline: 1.0504x; 1.0504x over previous
#include <cuda_runtime.h>

// ---------------- problem constants ----------------
#define B_    8
#define H_    192
#define W_    192
#define C_    128
#define DW_   256
#define NPIX  (B_*H_*W_)        // 294912
#define PIXPB (H_*W_)           // 36864 pixels per batch
#define EPS   1e-6f

// ---------------- launch geometry ----------------
#define WARPS      8
#define THREADS    256
#define PPW        4                         // pixels per warp per inner iter
#define ITERS      16
#define PIXPERBLK  (WARPS*PPW*ITERS)         // 512
#define NBLK       (NPIX/PIXPERBLK)          // 576
#define BLKPB      (PIXPB/PIXPERBLK)         // 72 blocks per batch (exact)

// ---------------- scratch (static device memory; no allocation) ----------------
__device__ float g_s[NPIX*C_];       // gated spatial branch (pre-SE)
__device__ float g_xm[NPIX*C_];      // x + beta*spatial  (input to FFN branch)
__device__ float g_gpart[NBLK*C_];   // per-block GAP partial sums (deterministic)
__device__ float g_att[B_*C_];       // SE attention per batch

// =====================================================================
// Kernel 1: LN1 -> w1 (128->256) + b1 -> dw affine -> SimpleGate -> g_s
//           + per-block per-channel partial sums for GAP
// =====================================================================
__global__ void __launch_bounds__(THREADS)
k1_spatial_gate(const float* __restrict__ x,
                const float* __restrict__ ln1s, const float* __restrict__ ln1b,
                const float* __restrict__ w1,   const float* __restrict__ b1,
                const float* __restrict__ wdw,  const float* __restrict__ bdw)
{
    extern __shared__ float sm[];
    float* w1s = sm;                      // 128*256 = 32768 floats
    float* ts  = sm + C_*DW_;             // 8 warps * 4 pix * 128 = 4096 floats
    __shared__ float gapb[C_];

    const int tid = threadIdx.x, wid = tid >> 5, lid = tid & 31;

    // stage w1 into smem (float4)
    for (int i = tid; i < (C_*DW_)/4; i += THREADS)
        ((float4*)w1s)[i] = ((const float4*)w1)[i];
    if (tid < C_) gapb[tid] = 0.f;

    // per-lane parameter vectors (lane owns channels 4*lid .. 4*lid+3; +128 for B half)
    const float4 l1s = ((const float4*)ln1s)[lid];
    const float4 l1b = ((const float4*)ln1b)[lid];
    const float4 b1A = ((const float4*)b1 )[lid];
    const float4 b1B = ((const float4*)b1 )[lid + 32];
    const float4 dwA = ((const float4*)wdw)[lid];
    const float4 dwB = ((const float4*)wdw)[lid + 32];
    const float4 dbA = ((const float4*)bdw)[lid];
    const float4 dbB = ((const float4*)bdw)[lid + 32];
    __syncthreads();

    float gl0 = 0.f, gl1 = 0.f, gl2 = 0.f, gl3 = 0.f;
    float* tw = ts + wid * (PPW*C_);

    for (int it = 0; it < ITERS; ++it) {
        const int p0 = blockIdx.x*PIXPERBLK + it*(WARPS*PPW) + wid*PPW;

        // --- LN1 and stage t into smem ---
        #pragma unroll
        for (int q = 0; q < PPW; ++q) {
            const int p = p0 + q;
            float4 xv = ((const float4*)x)[p*32 + lid];
            float s1 = xv.x + xv.y + xv.z + xv.w;
            float s2 = xv.x*xv.x + xv.y*xv.y + xv.z*xv.z + xv.w*xv.w;
            #pragma unroll
            for (int o = 16; o; o >>= 1) {
                s1 += __shfl_xor_sync(0xffffffffu, s1, o);
                s2 += __shfl_xor_sync(0xffffffffu, s2, o);
            }
            const float mu = s1 * (1.f/C_);
            const float rs = rsqrtf(fmaxf(s2*(1.f/C_) - mu*mu, 0.f) + EPS);
            float4 t;
            t.x = (xv.x - mu)*rs*l1s.x + l1b.x;
            t.y = (xv.y - mu)*rs*l1s.y + l1b.y;
            t.z = (xv.z - mu)*rs*l1s.z + l1b.z;
            t.w = (xv.w - mu)*rs*l1s.w + l1b.w;
            ((float4*)(tw + q*C_))[lid] = t;
        }
        __syncwarp();

        // --- u = t @ w1 : lane accumulates outputs {4lid..4lid+3} and {128+4lid..} ---
        float acc[PPW][8];
        #pragma unroll
        for (int q = 0; q < PPW; ++q)
            #pragma unroll
            for (int j = 0; j < 8; ++j) acc[q][j] = 0.f;

        #pragma unroll 4
        for (int k = 0; k < C_; ++k) {
            const float4 wa = ((const float4*)(w1s + k*DW_))[lid];
            const float4 wb = ((const float4*)(w1s + k*DW_ + C_))[lid];
            #pragma unroll
            for (int q = 0; q < PPW; ++q) {
                const float tk = tw[q*C_ + k];
                acc[q][0] += tk*wa.x; acc[q][1] += tk*wa.y;
                acc[q][2] += tk*wa.z; acc[q][3] += tk*wa.w;
                acc[q][4] += tk*wb.x; acc[q][5] += tk*wb.y;
                acc[q][6] += tk*wb.z; acc[q][7] += tk*wb.w;
            }
        }

        // --- +b1, dw affine, gate, store s, GAP partial ---
        #pragma unroll
        for (int q = 0; q < PPW; ++q) {
            const int p = p0 + q;
            float4 uA, uB, sv;
            uA.x = (acc[q][0] + b1A.x)*dwA.x + dbA.x;
            uA.y = (acc[q][1] + b1A.y)*dwA.y + dbA.y;
            uA.z = (acc[q][2] + b1A.z)*dwA.z + dbA.z;
            uA.w = (acc[q][3] + b1A.w)*dwA.w + dbA.w;
            uB.x = (acc[q][4] + b1B.x)*dwB.x + dbB.x;
            uB.y = (acc[q][5] + b1B.y)*dwB.y + dbB.y;
            uB.z = (acc[q][6] + b1B.z)*dwB.z + dbB.z;
            uB.w = (acc[q][7] + b1B.w)*dwB.w + dbB.w;
            sv.x = uA.x*uB.x; sv.y = uA.y*uB.y; sv.z = uA.z*uB.z; sv.w = uA.w*uB.w;
            ((float4*)g_s)[p*32 + lid] = sv;
            gl0 += sv.x; gl1 += sv.y; gl2 += sv.z; gl3 += sv.w;
        }
        __syncwarp();
    }

    // per-block channel sums (smem atomics across 8 warps; channel-aligned lanes)
    atomicAdd(&gapb[4*lid + 0], gl0);
    atomicAdd(&gapb[4*lid + 1], gl1);
    atomicAdd(&gapb[4*lid + 2], gl2);
    atomicAdd(&gapb[4*lid + 3], gl3);
    __syncthreads();
    if (tid < C_) g_gpart[blockIdx.x*C_ + tid] = gapb[tid];
}

// =====================================================================
// Kernel 2: deterministic GAP reduce + SE dense: att = (gap/PIXPB)@wse + bse
// grid = B_ blocks, 128 threads
// =====================================================================
__global__ void k2_se(const float* __restrict__ wse, const float* __restrict__ bse)
{
    __shared__ float gap[C_];
    const int b = blockIdx.x, j = threadIdx.x;
    float s = 0.f;
    for (int blk = 0; blk < BLKPB; ++blk)
        s += g_gpart[(b*BLKPB + blk)*C_ + j];
    gap[j] = s * (1.f/PIXPB);
    __syncthreads();
    float a = bse[j];
    #pragma unroll 4
    for (int k = 0; k < C_; ++k)
        a += gap[k] * wse[k*C_ + j];
    g_att[b*C_ + j] = a;
}

// =====================================================================
// Kernel 3a: v = s*att -> w2 (128->128) + b2 -> xm = x + beta*y
// =====================================================================
__global__ void __launch_bounds__(THREADS)
k3a_project(const float* __restrict__ x, const float* __restrict__ w2,
            const float* __restrict__ b2, const float* __restrict__ beta)
{
    extern __shared__ float sm[];
    float* w2s = sm;                 // 128*128 = 16384 floats
    float* ts  = sm + C_*C_;         // 4096 floats

    const int tid = threadIdx.x, wid = tid >> 5, lid = tid & 31;
    for (int i = tid; i < (C_*C_)/4; i += THREADS)
        ((float4*)w2s)[i] = ((const float4*)w2)[i];

    const int b = blockIdx.x / BLKPB;
    const float4 attv  = ((const float4*)(g_att + b*C_))[lid];
    const float4 b2v   = ((const float4*)b2  )[lid];
    const float4 betav = ((const float4*)beta)[lid];
    __syncthreads();

    float* tw = ts + wid * (PPW*C_);

    for (int it = 0; it < ITERS; ++it) {
        const int p0 = blockIdx.x*PIXPERBLK + it*(WARPS*PPW) + wid*PPW;
        #pragma unroll
        for (int q = 0; q < PPW; ++q) {
            const int p = p0 + q;
            float4 svv = ((const float4*)g_s)[p*32 + lid];
            float4 v;
            v.x = svv.x*attv.x; v.y = svv.y*attv.y; v.z = svv.z*attv.z; v.w = svv.w*attv.w;
            ((float4*)(tw + q*C_))[lid] = v;
        }
        __syncwarp();

        float acc[PPW][4];
        #pragma unroll
        for (int q = 0; q < PPW; ++q)
            #pragma unroll
            for (int j = 0; j < 4; ++j) acc[q][j] = 0.f;

        #pragma unroll 4
        for (int k = 0; k < C_; ++k) {
            const float4 w = ((const float4*)(w2s + k*C_))[lid];
            #pragma unroll
            for (int q = 0; q < PPW; ++q) {
                const float tk = tw[q*C_ + k];
                acc[q][0] += tk*w.x; acc[q][1] += tk*w.y;
                acc[q][2] += tk*w.z; acc[q][3] += tk*w.w;
            }
        }

        #pragma unroll
        for (int q = 0; q < PPW; ++q) {
            const int p = p0 + q;
            float4 xv = ((const float4*)x)[p*32 + lid];
            float4 xm;
            xm.x = xv.x + betav.x*(acc[q][0] + b2v.x);
            xm.y = xv.y + betav.y*(acc[q][1] + b2v.y);
            xm.z = xv.z + betav.z*(acc[q][2] + b2v.z);
            xm.w = xv.w + betav.w*(acc[q][3] + b2v.w);
            ((float4*)g_xm)[p*32 + lid] = xm;
        }
        __syncwarp();
    }
}

// =====================================================================
// Kernel 3b: LN2 -> wf1 (128->256)+bf1 -> gate -> wf2 (128->128)+bf2
//            -> out = xm + gamma*c
// =====================================================================
__global__ void __launch_bounds__(THREADS)
k3b_ffn(const float* __restrict__ ln2s, const float* __restrict__ ln2b,
        const float* __restrict__ wf1,  const float* __restrict__ bf1,
        const float* __restrict__ wf2,  const float* __restrict__ bf2,
        const float* __restrict__ gamma, float* __restrict__ out)
{
    extern __shared__ float sm[];
    float* wf1s = sm;                       // 32768 floats
    float* wf2s = sm + C_*DW_;              // 16384 floats
    float* ts   = sm + C_*DW_ + C_*C_;      // 4096 floats

    const int tid = threadIdx.x, wid = tid >> 5, lid = tid & 31;
    for (int i = tid; i < (C_*DW_)/4; i += THREADS)
        ((float4*)wf1s)[i] = ((const float4*)wf1)[i];
    for (int i = tid; i < (C_*C_)/4; i += THREADS)
        ((float4*)wf2s)[i] = ((const float4*)wf2)[i];

    const float4 l2s  = ((const float4*)ln2s)[lid];
    const float4 l2b  = ((const float4*)ln2b)[lid];
    const float4 bf1A = ((const float4*)bf1)[lid];
    const float4 bf1B = ((const float4*)bf1)[lid + 32];
    const float4 bf2v = ((const float4*)bf2)[lid];
    const float4 gamv = ((const float4*)gamma)[lid];
    __syncthreads();

    float* tw = ts + wid * (PPW*C_);

    for (int it = 0; it < ITERS; ++it) {
        const int p0 = blockIdx.x*PIXPERBLK + it*(WARPS*PPW) + wid*PPW;

        float4 xm[PPW];
        #pragma unroll
        for (int q = 0; q < PPW; ++q) {
            const int p = p0 + q;
            xm[q] = ((const float4*)g_xm)[p*32 + lid];
            float s1 = xm[q].x + xm[q].y + xm[q].z + xm[q].w;
            float s2 = xm[q].x*xm[q].x + xm[q].y*xm[q].y + xm[q].z*xm[q].z + xm[q].w*xm[q].w;
            #pragma unroll
            for (int o = 16; o; o >>= 1) {
                s1 += __shfl_xor_sync(0xffffffffu, s1, o);
                s2 += __shfl_xor_sync(0xffffffffu, s2, o);
            }
            const float mu = s1 * (1.f/C_);
            const float rs = rsqrtf(fmaxf(s2*(1.f/C_) - mu*mu, 0.f) + EPS);
            float4 t;
            t.x = (xm[q].x - mu)*rs*l2s.x + l2b.x;
            t.y = (xm[q].y - mu)*rs*l2s.y + l2b.y;
            t.z = (xm[q].z - mu)*rs*l2s.z + l2b.z;
            t.w = (xm[q].w - mu)*rs*l2s.w + l2b.w;
            ((float4*)(tw + q*C_))[lid] = t;
        }
        __syncwarp();

        // u = t @ wf1
        float acc[PPW][8];
        #pragma unroll
        for (int q = 0; q < PPW; ++q)
            #pragma unroll
            for (int j = 0; j < 8; ++j) acc[q][j] = 0.f;

        #pragma unroll 4
        for (int k = 0; k < C_; ++k) {
            const float4 wa = ((const float4*)(wf1s + k*DW_))[lid];
            const float4 wb = ((const float4*)(wf1s + k*DW_ + C_))[lid];
            #pragma unroll
            for (int q = 0; q < PPW; ++q) {
                const float tk = tw[q*C_ + k];
                acc[q][0] += tk*wa.x; acc[q][1] += tk*wa.y;
                acc[q][2] += tk*wa.z; acc[q][3] += tk*wa.w;
                acc[q][4] += tk*wb.x; acc[q][5] += tk*wb.y;
                acc[q][6] += tk*wb.z; acc[q][7] += tk*wb.w;
            }
        }
        __syncwarp();

        // gate, restage c into ts
        #pragma unroll
        for (int q = 0; q < PPW; ++q) {
            float4 uA, uB, cv;
            uA.x = acc[q][0] + bf1A.x; uA.y = acc[q][1] + bf1A.y;
            uA.z = acc[q][2] + bf1A.z; uA.w = acc[q][3] + bf1A.w;
            uB.x = acc[q][4] + bf1B.x; uB.y = acc[q][5] + bf1B.y;
            uB.z = acc[q][6] + bf1B.z; uB.w = acc[q][7] + bf1B.w;
            cv.x = uA.x*uB.x; cv.y = uA.y*uB.y; cv.z = uA.z*uB.z; cv.w = uA.w*uB.w;
            ((float4*)(tw + q*C_))[lid] = cv;
        }
        __syncwarp();

        // z = c @ wf2
        float acc2[PPW][4];
        #pragma unroll
        for (int q = 0; q < PPW; ++q)
            #pragma unroll
            for (int j = 0; j < 4; ++j) acc2[q][j] = 0.f;

        #pragma unroll 4
        for (int k = 0; k < C_; ++k) {
            const float4 w = ((const float4*)(wf2s + k*C_))[lid];
            #pragma unroll
            for (int q = 0; q < PPW; ++q) {
                const float tk = tw[q*C_ + k];
                acc2[q][0] += tk*w.x; acc2[q][1] += tk*w.y;
                acc2[q][2] += tk*w.z; acc2[q][3] += tk*w.w;
            }
        }

        #pragma unroll
        for (int q = 0; q < PPW; ++q) {
            const int p = p0 + q;
            float4 o;
            o.x = xm[q].x + gamv.x*(acc2[q][0] + bf2v.x);
            o.y = xm[q].y + gamv.y*(acc2[q][1] + bf2v.y);
            o.z = xm[q].z + gamv.z*(acc2[q][2] + bf2v.z);
            o.w = xm[q].w + gamv.w*(acc2[q][3] + bf2v.w);
            ((float4*)out)[p*32 + lid] = o;
        }
        __syncwarp();
    }
}

// =====================================================================
// launch
// =====================================================================
extern "C" void kernel_launch(void* const* d_in, const int* in_sizes, int n_in,
                              void* d_out, int out_size)
{
    (void)in_sizes; (void)n_in; (void)out_size;
    const float* x     = (const float*)d_in[0];
    const float* ln1s  = (const float*)d_in[1];
    const float* ln1b  = (const float*)d_in[2];
    const float* w1    = (const float*)d_in[3];
    const float* b1    = (const float*)d_in[4];
    const float* wdw   = (const float*)d_in[5];
    const float* bdw   = (const float*)d_in[6];
    const float* wse   = (const float*)d_in[7];
    const float* bse   = (const float*)d_in[8];
    const float* w2    = (const float*)d_in[9];
    const float* b2    = (const float*)d_in[10];
    const float* ln2s  = (const float*)d_in[11];
    const float* ln2b  = (const float*)d_in[12];
    const float* wf1   = (const float*)d_in[13];
    const float* bf1   = (const float*)d_in[14];
    const float* wf2   = (const float*)d_in[15];
    const float* bf2   = (const float*)d_in[16];
    const float* beta  = (const float*)d_in[17];
    const float* gamma = (const float*)d_in[18];
    float* out = (float*)d_out;

    const size_t smem1  = (size_t)(C_*DW_ + WARPS*PPW*C_) * 4;            // 147456
    const size_t smem3a = (size_t)(C_*C_  + WARPS*PPW*C_) * 4;            // 81920
    const size_t smem3b = (size_t)(C_*DW_ + C_*C_ + WARPS*PPW*C_) * 4;    // 212992

    cudaFuncSetAttribute(k1_spatial_gate, cudaFuncAttributeMaxDynamicSharedMemorySize, (int)smem1);
    cudaFuncSetAttribute(k3a_project,     cudaFuncAttributeMaxDynamicSharedMemorySize, (int)smem3a);
    cudaFuncSetAttribute(k3b_ffn,         cudaFuncAttributeMaxDynamicSharedMemorySize, (int)smem3b);

    k1_spatial_gate<<<NBLK, THREADS, smem1>>>(x, ln1s, ln1b, w1, b1, wdw, bdw);
    k2_se<<<B_, C_>>>(wse, bse);
    k3a_project<<<NBLK, THREADS, smem3a>>>(x, w2, b2, beta);
    k3b_ffn<<<NBLK, THREADS, smem3b>>>(ln2s, ln2b, wf1, bf1, wf2, bf2, gamma, out);
}

// round 5
// speedup vs baseline: 3.7270x; 3.5482x over previous
#include <cuda_runtime.h>
#include <cuda_bf16.h>
#include <cstdint>

#define B_     8
#define C_     128
#define PIXPB  36864
#define NPIX   294912
#define NT     2304             // 128-pixel tiles
#define TPB    288              // tiles per batch
#define EPS    1e-6f
#define GRID_P 148
#define SA     304              // A-tile row stride bytes (conflict-friendly)

// ---------------- device globals (no allocation) ----------------
__device__ uint32_t g_s[(size_t)NPIX * 64];   // gated branch bf16x2 [pix][64]
__device__ float    g_gpart[576 * 128];
__device__ float    g_att[B_ * C_];
// mma.sync B-fragment images: [ks][nb][e][lane] uint32 (bf16x2)
__device__ uint32_t g_fw1 [8 * 32 * 2 * 32];  // w1  (pair-permuted), N=256
__device__ uint32_t g_fwf1[8 * 32 * 2 * 32];  // wf1 (pair-permuted), N=256
__device__ uint32_t g_fw2 [8 * 16 * 2 * 32];  // w2, N=128
__device__ uint32_t g_fwf2[8 * 16 * 2 * 32];  // wf2, N=128

__device__ __forceinline__ uint32_t pack_bf2(float a, float b) {
    __nv_bfloat162 h = __floats2bfloat162_rn(a, b);   // low = a
    return *reinterpret_cast<uint32_t*>(&h);
}
__device__ __forceinline__ float2 unpack_bf2(uint32_t w) {
    __nv_bfloat162 h = *reinterpret_cast<const __nv_bfloat162*>(&w);
    return make_float2(__low2float(h), __high2float(h));
}
__device__ __forceinline__ void mma_bf16(float* c, uint32_t a0, uint32_t a1,
                                         uint32_t a2, uint32_t a3,
                                         uint32_t b0, uint32_t b1) {
    asm volatile(
        "mma.sync.aligned.m16n8k16.row.col.f32.bf16.bf16.f32 "
        "{%0,%1,%2,%3}, {%4,%5,%6,%7}, {%8,%9}, {%0,%1,%2,%3};\n"
        : "+f"(c[0]), "+f"(c[1]), "+f"(c[2]), "+f"(c[3])
        : "r"(a0), "r"(a1), "r"(a2), "r"(a3), "r"(b0), "r"(b1));
}

// =====================================================================
// k0: build B-fragment images in mma.sync register layout.
// B frag (m16n8k16, col): lane holds B[k][n], n = lane/4, k = 2*(lane%4)+{0,1} (+8 for e=1)
// w1/wf1 use paired columns: img col n -> orig col (n>>1) + (n&1)*128
// =====================================================================
__global__ void k0_frags(const float* __restrict__ w1, const float* __restrict__ w2,
                         const float* __restrict__ wf1, const float* __restrict__ wf2)
{
    int i0 = blockIdx.x * blockDim.x + threadIdx.x, str = gridDim.x * blockDim.x;
    for (int i = i0; i < 8 * 32 * 2 * 32; i += str) {
        int lane = i & 31, e = (i >> 5) & 1, nb = (i >> 6) & 31, ks = i >> 11;
        int n = 8 * nb + (lane >> 2);
        int k = 16 * ks + 2 * (lane & 3) + 8 * e;
        int o = (n >> 1) + (n & 1) * 128;
        g_fw1 [i] = pack_bf2(w1 [k * 256 + o], w1 [(k + 1) * 256 + o]);
        g_fwf1[i] = pack_bf2(wf1[k * 256 + o], wf1[(k + 1) * 256 + o]);
    }
    for (int i = i0; i < 8 * 16 * 2 * 32; i += str) {
        int lane = i & 31, e = (i >> 5) & 1, nb = (i >> 6) & 15, ks = i >> 10;
        int n = 8 * nb + (lane >> 2);
        int k = 16 * ks + 2 * (lane & 3) + 8 * e;
        g_fw2 [i] = pack_bf2(w2 [k * 128 + n], w2 [(k + 1) * 128 + n]);
        g_fwf2[i] = pack_bf2(wf2[k * 128 + n], wf2[(k + 1) * 128 + n]);
    }
}

// =====================================================================
// kA: LN1 -> mma(w1 paired, N=256) -> dw-affine + gate -> g_s (bf16)
// smem: atile[128*SA] | fw1 64KB | ew f2[256] | ln f2[128]
// =====================================================================
#define KA_FW1  38912
#define KA_EW   (KA_FW1 + 65536)
#define KA_LN   (KA_EW + 2048)
#define KA_SMEM (KA_LN + 1024)

__global__ void __launch_bounds__(256, 1)
kA_spatial(const float* __restrict__ x,
           const float* __restrict__ ln1s, const float* __restrict__ ln1b,
           const float* __restrict__ b1,   const float* __restrict__ wdw,
           const float* __restrict__ bdw)
{
    extern __shared__ char sm[];
    const int tid = threadIdx.x, lane = tid & 31, warp = tid >> 5;
    const int q = lane & 3, r = lane >> 2, m0 = warp * 16;

    {
        uint4* dst = (uint4*)(sm + KA_FW1);
        const uint4* src = (const uint4*)g_fw1;
        for (int i = tid; i < 4096; i += 256) dst[i] = src[i];
        if (tid < 256) {
            int n = tid, o = (n >> 1) + (n & 1) * 128;
            float w = wdw[o];
            ((float2*)(sm + KA_EW))[n] = make_float2(w, b1[o] * w + bdw[o]);
        }
        if (tid < 128)
            ((float2*)(sm + KA_LN))[tid] = make_float2(ln1s[tid], ln1b[tid]);
    }
    __syncthreads();

    const uint32_t* fw1s = (const uint32_t*)(sm + KA_FW1);
    const float2* ewp = (const float2*)(sm + KA_EW);
    const float2* lnp = (const float2*)(sm + KA_LN);
    const int pl = tid >> 1, h = tid & 1;    // LN thread mapping (warp-local rows)

    for (int tile = blockIdx.x; tile < NT; tile += GRID_P) {
        // ---- LN1: thread handles pixel pl, channels h*64..h*64+63 ----
        const float4* xr = (const float4*)x + ((size_t)(tile * 128 + pl)) * 32 + h * 16;
        float4 xv[16];
        float s1 = 0.f, s2 = 0.f;
        #pragma unroll
        for (int i = 0; i < 16; ++i) {
            xv[i] = xr[i];
            s1 += xv[i].x + xv[i].y + xv[i].z + xv[i].w;
            s2 += xv[i].x*xv[i].x + xv[i].y*xv[i].y + xv[i].z*xv[i].z + xv[i].w*xv[i].w;
        }
        s1 += __shfl_xor_sync(0xffffffffu, s1, 1);
        s2 += __shfl_xor_sync(0xffffffffu, s2, 1);
        const float mu = s1 * (1.f/128.f);
        const float rs = rsqrtf(fmaxf(s2 * (1.f/128.f) - mu*mu, 0.f) + EPS);

        char* rowb = sm + pl * SA + h * 128;
        #pragma unroll
        for (int j = 0; j < 8; ++j) {
            float4 v0 = xv[2*j], v1 = xv[2*j+1];
            int c = h * 64 + 8 * j;
            float2 p0 = lnp[c],   p1 = lnp[c+1], p2 = lnp[c+2], p3 = lnp[c+3];
            float2 p4 = lnp[c+4], p5 = lnp[c+5], p6 = lnp[c+6], p7 = lnp[c+7];
            uint4 o;
            o.x = pack_bf2((v0.x-mu)*rs*p0.x+p0.y, (v0.y-mu)*rs*p1.x+p1.y);
            o.y = pack_bf2((v0.z-mu)*rs*p2.x+p2.y, (v0.w-mu)*rs*p3.x+p3.y);
            o.z = pack_bf2((v1.x-mu)*rs*p4.x+p4.y, (v1.y-mu)*rs*p5.x+p5.y);
            o.w = pack_bf2((v1.z-mu)*rs*p6.x+p6.y, (v1.w-mu)*rs*p7.x+p7.y);
            *(uint4*)(rowb + j * 16) = o;
        }
        __syncwarp();

        // ---- GEMM1: warp tile m16 x n256 ----
        float acc[32][4];
        #pragma unroll
        for (int nb = 0; nb < 32; ++nb)
            { acc[nb][0]=0.f; acc[nb][1]=0.f; acc[nb][2]=0.f; acc[nb][3]=0.f; }

        const char* ar0 = sm + (m0 + r) * SA;
        #pragma unroll 1
        for (int ks = 0; ks < 8; ++ks) {
            int kb = 32 * ks + 4 * q;
            uint32_t a0 = *(const uint32_t*)(ar0 + kb);
            uint32_t a1 = *(const uint32_t*)(ar0 + 8 * SA + kb);
            uint32_t a2 = *(const uint32_t*)(ar0 + kb + 16);
            uint32_t a3 = *(const uint32_t*)(ar0 + 8 * SA + kb + 16);
            const uint32_t* fb = fw1s + ks * 2048 + lane;
            #pragma unroll
            for (int nb = 0; nb < 32; ++nb)
                mma_bf16(acc[nb], a0, a1, a2, a3, fb[nb*64], fb[nb*64+32]);
        }
        __syncwarp();

        // ---- gate: s[j] = u[2j]*u[2j+1], j = 4nb+q; write bf16 rows ----
        #pragma unroll
        for (int nb = 0; nb < 32; ++nb) {
            int n0 = 8 * nb + 2 * q, j = 4 * nb + q;
            float2 e0 = ewp[n0], e1 = ewp[n0 + 1];
            float lo = (acc[nb][0]*e0.x + e0.y) * (acc[nb][1]*e1.x + e1.y);
            float hi = (acc[nb][2]*e0.x + e0.y) * (acc[nb][3]*e1.x + e1.y);
            *(__nv_bfloat16*)(sm + (m0 + r)     * SA + j * 2) = __float2bfloat16(lo);
            *(__nv_bfloat16*)(sm + (m0 + r + 8) * SA + j * 2) = __float2bfloat16(hi);
        }
        __syncwarp();

        // ---- coalesced copy to g_s ----
        #pragma unroll
        for (int i = 0; i < 8; ++i) {
            int u = lane + 32 * i, row = u >> 4, ch = u & 15;
            uint4 v = *(const uint4*)(sm + (m0 + row) * SA + ch * 16);
            ((uint4*)g_s)[((size_t)(tile * 128 + m0 + row)) * 16 + ch] = v;
        }
        __syncwarp();
    }
}

// =====================================================================
// k2_gap / k2_se: deterministic GAP + SE
// =====================================================================
__global__ void k2_gap()
{
    __shared__ float red[2][128];
    const int t = threadIdx.x, w = t & 63, h = t >> 6;
    const int base = blockIdx.x * 512 + h * 256;
    float a0 = 0.f, a1 = 0.f;
    #pragma unroll 8
    for (int i = 0; i < 256; ++i) {
        float2 v = unpack_bf2(g_s[(size_t)(base + i) * 64 + w]);
        a0 += v.x; a1 += v.y;
    }
    red[h][2*w] = a0; red[h][2*w+1] = a1;
    __syncthreads();
    if (t < 128) g_gpart[blockIdx.x * 128 + t] = red[0][t] + red[1][t];
}

__global__ void k2_se(const float* __restrict__ wse, const float* __restrict__ bse)
{
    __shared__ float gap[128];
    const int b = blockIdx.x, j = threadIdx.x;
    float s = 0.f;
    for (int blk = 0; blk < 72; ++blk) s += g_gpart[(b * 72 + blk) * 128 + j];
    gap[j] = s * (1.f / PIXPB);
    __syncthreads();
    float a = bse[j];
    #pragma unroll 4
    for (int k = 0; k < 128; ++k) a += gap[k] * wse[k * 128 + j];
    g_att[b * 128 + j] = a;
}

// =====================================================================
// kB: v=s*att -> mma(w2) -> xm=x+beta*(d+b2) (f32 smem) + LN2 ->
//     mma(wf1 paired) -> gate -> mma(wf2) -> out = xm + gamma*(d+bf2)
// smem: atile 38912 | xm f32[128][132] 67584 | fwf1 64K | fw2 32K | params
// =====================================================================
#define KB_XM    38912
#define KB_FWF1  (KB_XM + 67584)
#define KB_FW2   (KB_FWF1 + 65536)
#define KB_E2    (KB_FW2 + 32768)
#define KB_ELN   (KB_E2 + 1024)
#define KB_EBF1  (KB_ELN + 1024)
#define KB_EGAM  (KB_EBF1 + 1024)
#define KB_SMEM  (KB_EGAM + 1024)

__global__ void __launch_bounds__(256, 1)
kB_ffn(const float* __restrict__ x,
       const float* __restrict__ b2,   const float* __restrict__ beta,
       const float* __restrict__ ln2s, const float* __restrict__ ln2b,
       const float* __restrict__ bf1,  const float* __restrict__ bf2,
       const float* __restrict__ gamma, float* __restrict__ out)
{
    extern __shared__ char sm[];
    const int tid = threadIdx.x, lane = tid & 31, warp = tid >> 5;
    const int q = lane & 3, r = lane >> 2, m0 = warp * 16;

    {
        uint4* d1 = (uint4*)(sm + KB_FWF1);
        const uint4* s1p = (const uint4*)g_fwf1;
        for (int i = tid; i < 4096; i += 256) d1[i] = s1p[i];
        uint4* d2 = (uint4*)(sm + KB_FW2);
        const uint4* s2p = (const uint4*)g_fw2;
        for (int i = tid; i < 2048; i += 256) d2[i] = s2p[i];
        if (tid < 128) {
            float be = beta[tid], ga = gamma[tid];
            ((float2*)(sm + KB_E2  ))[tid] = make_float2(be, be * b2[tid]);
            ((float2*)(sm + KB_ELN ))[tid] = make_float2(ln2s[tid], ln2b[tid]);
            ((float2*)(sm + KB_EGAM))[tid] = make_float2(ga, ga * bf2[tid]);
        }
        if (tid < 256) {
            int n = tid, o = (n >> 1) + (n & 1) * 128;
            ((float*)(sm + KB_EBF1))[n] = bf1[o];
        }
    }
    __syncthreads();

    const uint32_t* fwf1s = (const uint32_t*)(sm + KB_FWF1);
    const uint32_t* fw2s  = (const uint32_t*)(sm + KB_FW2);
    const float2* e2p  = (const float2*)(sm + KB_E2);
    const float2* elnp = (const float2*)(sm + KB_ELN);
    const float*  ebfp = (const float*)(sm + KB_EBF1);
    const float2* egap = (const float2*)(sm + KB_EGAM);
    float* xms = (float*)(sm + KB_XM);
    const int pl = tid >> 1, h = tid & 1;

    for (int tile = blockIdx.x; tile < NT; tile += GRID_P) {
        const int batch = tile / TPB;

        // ---- stage A = s * att (bf16): 8 uint4 = full 64-channel half ----
        {
            const uint4* sr = (const uint4*)g_s + ((size_t)(tile * 128 + pl)) * 16 + h * 8;
            const float4* attr = (const float4*)(g_att + batch * 128 + h * 64);
            char* rowb = sm + pl * SA + h * 128;
            #pragma unroll
            for (int j = 0; j < 8; ++j) {
                uint4 sv = sr[j];
                float4 aA = attr[2*j], aB = attr[2*j+1];
                float2 v0 = unpack_bf2(sv.x), v1 = unpack_bf2(sv.y);
                float2 v2 = unpack_bf2(sv.z), v3 = unpack_bf2(sv.w);
                uint4 o;
                o.x = pack_bf2(v0.x * aA.x, v0.y * aA.y);
                o.y = pack_bf2(v1.x * aA.z, v1.y * aA.w);
                o.z = pack_bf2(v2.x * aB.x, v2.y * aB.y);
                o.w = pack_bf2(v3.x * aB.z, v3.y * aB.w);
                *(uint4*)(rowb + j * 16) = o;
            }
        }
        __syncwarp();

        const char* ar0 = sm + (m0 + r) * SA;

        // ---- GEMM w2 (n128) ----
        float acc[16][4];
        #pragma unroll
        for (int nb = 0; nb < 16; ++nb)
            { acc[nb][0]=0.f; acc[nb][1]=0.f; acc[nb][2]=0.f; acc[nb][3]=0.f; }
        #pragma unroll 1
        for (int ks = 0; ks < 8; ++ks) {
            int kb = 32 * ks + 4 * q;
            uint32_t a0 = *(const uint32_t*)(ar0 + kb);
            uint32_t a1 = *(const uint32_t*)(ar0 + 8 * SA + kb);
            uint32_t a2 = *(const uint32_t*)(ar0 + kb + 16);
            uint32_t a3 = *(const uint32_t*)(ar0 + 8 * SA + kb + 16);
            const uint32_t* fb = fw2s + ks * 1024 + lane;
            #pragma unroll
            for (int nb = 0; nb < 16; ++nb)
                mma_bf16(acc[nb], a0, a1, a2, a3, fb[nb*64], fb[nb*64+32]);
        }

        // ---- xm = x + beta*(d+b2); stash f32; LN2 stats via quad shfl ----
        const float* xr0 = x + ((size_t)(tile * 128 + m0 + r)) * 128;
        const float* xr8 = xr0 + (size_t)8 * 128;
        float s1a = 0.f, s2a = 0.f, s1b = 0.f, s2b = 0.f;
        #pragma unroll
        for (int nb = 0; nb < 16; ++nb) {
            int n0 = 8 * nb + 2 * q;
            float2 e0 = e2p[n0], e1 = e2p[n0 + 1];
            float2 xa = *(const float2*)(xr0 + n0);
            float2 xb = *(const float2*)(xr8 + n0);
            float m00 = xa.x + acc[nb][0]*e0.x + e0.y;
            float m01 = xa.y + acc[nb][1]*e1.x + e1.y;
            float m10 = xb.x + acc[nb][2]*e0.x + e0.y;
            float m11 = xb.y + acc[nb][3]*e1.x + e1.y;
            *(float2*)(xms + (m0 + r)     * 132 + n0) = make_float2(m00, m01);
            *(float2*)(xms + (m0 + r + 8) * 132 + n0) = make_float2(m10, m11);
            s1a += m00 + m01; s2a += m00*m00 + m01*m01;
            s1b += m10 + m11; s2b += m10*m10 + m11*m11;
        }
        s1a += __shfl_xor_sync(0xffffffffu, s1a, 1); s1a += __shfl_xor_sync(0xffffffffu, s1a, 2);
        s2a += __shfl_xor_sync(0xffffffffu, s2a, 1); s2a += __shfl_xor_sync(0xffffffffu, s2a, 2);
        s1b += __shfl_xor_sync(0xffffffffu, s1b, 1); s1b += __shfl_xor_sync(0xffffffffu, s1b, 2);
        s2b += __shfl_xor_sync(0xffffffffu, s2b, 1); s2b += __shfl_xor_sync(0xffffffffu, s2b, 2);
        const float mua = s1a * (1.f/128.f);
        const float rsa = rsqrtf(fmaxf(s2a * (1.f/128.f) - mua*mua, 0.f) + EPS);
        const float mub = s1b * (1.f/128.f);
        const float rsb = rsqrtf(fmaxf(s2b * (1.f/128.f) - mub*mub, 0.f) + EPS);

        // ---- A2 = LN2(xm) -> atile bf16 ----
        #pragma unroll
        for (int nb = 0; nb < 16; ++nb) {
            int n0 = 8 * nb + 2 * q;
            float2 p0 = elnp[n0], p1 = elnp[n0 + 1];
            float2 va = *(const float2*)(xms + (m0 + r)     * 132 + n0);
            float2 vb = *(const float2*)(xms + (m0 + r + 8) * 132 + n0);
            *(uint32_t*)(sm + (m0 + r)     * SA + n0 * 2) =
                pack_bf2((va.x-mua)*rsa*p0.x+p0.y, (va.y-mua)*rsa*p1.x+p1.y);
            *(uint32_t*)(sm + (m0 + r + 8) * SA + n0 * 2) =
                pack_bf2((vb.x-mub)*rsb*p0.x+p0.y, (vb.y-mub)*rsb*p1.x+p1.y);
        }
        __syncwarp();

        // ---- GEMM wf1 (paired, n256) ----
        float acc2[32][4];
        #pragma unroll
        for (int nb = 0; nb < 32; ++nb)
            { acc2[nb][0]=0.f; acc2[nb][1]=0.f; acc2[nb][2]=0.f; acc2[nb][3]=0.f; }
        #pragma unroll 1
        for (int ks = 0; ks < 8; ++ks) {
            int kb = 32 * ks + 4 * q;
            uint32_t a0 = *(const uint32_t*)(ar0 + kb);
            uint32_t a1 = *(const uint32_t*)(ar0 + 8 * SA + kb);
            uint32_t a2 = *(const uint32_t*)(ar0 + kb + 16);
            uint32_t a3 = *(const uint32_t*)(ar0 + 8 * SA + kb + 16);
            const uint32_t* fb = fwf1s + ks * 2048 + lane;
            #pragma unroll
            for (int nb = 0; nb < 32; ++nb)
                mma_bf16(acc2[nb], a0, a1, a2, a3, fb[nb*64], fb[nb*64+32]);
        }
        __syncwarp();

        // ---- gate -> atile bf16 (ch j = 4nb+q) ----
        #pragma unroll
        for (int nb = 0; nb < 32; ++nb) {
            int n0 = 8 * nb + 2 * q, j = 4 * nb + q;
            float e0 = ebfp[n0], e1 = ebfp[n0 + 1];
            float lo = (acc2[nb][0] + e0) * (acc2[nb][1] + e1);
            float hi = (acc2[nb][2] + e0) * (acc2[nb][3] + e1);
            *(__nv_bfloat16*)(sm + (m0 + r)     * SA + j * 2) = __float2bfloat16(lo);
            *(__nv_bfloat16*)(sm + (m0 + r + 8) * SA + j * 2) = __float2bfloat16(hi);
        }
        __syncwarp();

        // ---- GEMM wf2 (n128), frags via LDG ----
        float acc3[16][4];
        #pragma unroll
        for (int nb = 0; nb < 16; ++nb)
            { acc3[nb][0]=0.f; acc3[nb][1]=0.f; acc3[nb][2]=0.f; acc3[nb][3]=0.f; }
        #pragma unroll 1
        for (int ks = 0; ks < 8; ++ks) {
            int kb = 32 * ks + 4 * q;
            uint32_t a0 = *(const uint32_t*)(ar0 + kb);
            uint32_t a1 = *(const uint32_t*)(ar0 + 8 * SA + kb);
            uint32_t a2 = *(const uint32_t*)(ar0 + kb + 16);
            uint32_t a3 = *(const uint32_t*)(ar0 + 8 * SA + kb + 16);
            const uint32_t* fb = g_fwf2 + ks * 1024 + lane;
            #pragma unroll
            for (int nb = 0; nb < 16; ++nb)
                mma_bf16(acc3[nb], a0, a1, a2, a3, __ldg(fb + nb*64), __ldg(fb + nb*64 + 32));
        }

        // ---- out = xm + gamma*(d+bf2) ----
        float* or0 = out + ((size_t)(tile * 128 + m0 + r)) * 128;
        float* or8 = or0 + (size_t)8 * 128;
        #pragma unroll
        for (int nb = 0; nb < 16; ++nb) {
            int n0 = 8 * nb + 2 * q;
            float2 g0 = egap[n0], g1 = egap[n0 + 1];
            float2 va = *(const float2*)(xms + (m0 + r)     * 132 + n0);
            float2 vb = *(const float2*)(xms + (m0 + r + 8) * 132 + n0);
            *(float2*)(or0 + n0) = make_float2(va.x + acc3[nb][0]*g0.x + g0.y,
                                               va.y + acc3[nb][1]*g1.x + g1.y);
            *(float2*)(or8 + n0) = make_float2(vb.x + acc3[nb][2]*g0.x + g0.y,
                                               vb.y + acc3[nb][3]*g1.x + g1.y);
        }
        __syncwarp();
    }
}

// =====================================================================
// launch
// =====================================================================
extern "C" void kernel_launch(void* const* d_in, const int* in_sizes, int n_in,
                              void* d_out, int out_size)
{
    (void)in_sizes; (void)n_in; (void)out_size;
    const float* x     = (const float*)d_in[0];
    const float* ln1s  = (const float*)d_in[1];
    const float* ln1b  = (const float*)d_in[2];
    const float* w1    = (const float*)d_in[3];
    const float* b1    = (const float*)d_in[4];
    const float* wdw   = (const float*)d_in[5];
    const float* bdw   = (const float*)d_in[6];
    const float* wse   = (const float*)d_in[7];
    const float* bse   = (const float*)d_in[8];
    const float* w2    = (const float*)d_in[9];
    const float* b2    = (const float*)d_in[10];
    const float* ln2s  = (const float*)d_in[11];
    const float* ln2b  = (const float*)d_in[12];
    const float* wf1   = (const float*)d_in[13];
    const float* bf1   = (const float*)d_in[14];
    const float* wf2   = (const float*)d_in[15];
    const float* bf2   = (const float*)d_in[16];
    const float* beta  = (const float*)d_in[17];
    const float* gamma = (const float*)d_in[18];
    float* out = (float*)d_out;

    cudaFuncSetAttribute(kA_spatial, cudaFuncAttributeMaxDynamicSharedMemorySize, KA_SMEM);
    cudaFuncSetAttribute(kB_ffn,     cudaFuncAttributeMaxDynamicSharedMemorySize, KB_SMEM);

    k0_frags<<<64, 256>>>(w1, w2, wf1, wf2);
    kA_spatial<<<GRID_P, 256, KA_SMEM>>>(x, ln1s, ln1b, b1, wdw, bdw);
    k2_gap<<<576, 128>>>();
    k2_se<<<B_, 128>>>(wse, bse);
    kB_ffn<<<GRID_P, 256, KB_SMEM>>>(x, b2, beta, ln2s, ln2b, bf1, bf2, gamma, out);
}